// round 16
// baseline (speedup 1.0000x reference)
#include <cuda_runtime.h>
#include <cstdint>

// Problem dims
#define MDIM 8192
#define NDIM 4096
#define KDIM 4096

// Tiling: CTA 256x128 with 512 threads, thread tile 8x8 (4 m-pairs x 8 n)
#define BM 256
#define BN 128
#define BK 8
#define NKT (KDIM / BK)        // 512
#define HALF_TILES 256         // k=2048 boundary

#define AROW 264               // 256 + 8 pad floats
#define BROW 132               // 128 + 4 pad floats
#define ABUF (BK * AROW)       // 2112 floats
#define BBUF (BK * BROW)       // 1056 floats
#define BS_OFFF (2 * ABUF)
#define SPILL_OFF ((2 * ABUF + 2 * BBUF) * 4)        // 25344 bytes
#define SMEM_BYTES (SPILL_OFF + 512 * 32 * 8)        // 156416

// Reference chain (bitwise-locked): per output two ascending FMA chains over
// k-halves of 2048 (each from 0), merged with one add, +bias, truncated fmod.
// f32x2 lanes carry two DIFFERENT outputs (adjacent m) -> per-output chain
// bit-identical to scalar.

__device__ __forceinline__ float fmod2f(float v) {
    return fmaf(-2.0f, truncf(v * 0.5f), v);
}
__device__ __forceinline__ void ffma2(unsigned long long& d,
                                      unsigned long long a,
                                      unsigned long long b) {
    asm("fma.rn.f32x2 %0, %1, %2, %0;" : "+l"(d) : "l"(a), "l"(b));
}
__device__ __forceinline__ unsigned long long addf32x2(unsigned long long a,
                                                       unsigned long long b) {
    unsigned long long d;
    asm("add.rn.f32x2 %0, %1, %2;" : "=l"(d) : "l"(a), "l"(b));
    return d;
}
__device__ __forceinline__ unsigned long long dup2(float b) {
    unsigned long long d;
    asm("mov.b64 %0, {%1, %1};" : "=l"(d) : "f"(b));
    return d;
}

__global__ void __launch_bounds__(512, 1)
k_sgemm_fmod(const float* __restrict__ X, const float* __restrict__ W,
             const float* __restrict__ bias, float* __restrict__ out) {
    extern __shared__ char smem[];
    float* As = (float*)smem;                      // [2][8][264]
    float* Bs = As + BS_OFFF;                      // [2][8][132]
    unsigned long long* spill =
        (unsigned long long*)(smem + SPILL_OFF);   // [512][32]

    const int tid = threadIdx.x;
    const int tx = tid & 15;          // n: 16 thr x 8 cols
    const int ty = tid >> 4;          // m: 32 thr x 8 rows
    const int m0 = blockIdx.y * BM;
    const int n0 = blockIdx.x * BN;

    // loaders: A = 512 float4 chunks (1/thread); B = 256 chunks (tid<256)
    const int ar = tid >> 1, aq = tid & 1;
    const float* ga = X + (size_t)(m0 + ar) * KDIM + aq * 4;
    const bool hasB = tid < 256;
    const int br = (tid & 255) >> 1, bq = tid & 1;
    const float* gb = W + (size_t)(n0 + br) * KDIM + bq * 4;

    unsigned long long acc[4][8];   // 4 m-pairs x 8 n
#pragma unroll
    for (int i = 0; i < 4; i++)
#pragma unroll
        for (int j = 0; j < 8; j++) acc[i][j] = 0ull;

    // prologue: tile 0 -> buf 0
    {
        float4 a0 = *(const float4*)ga;
        float* d0 = As + aq * 4 * AROW + ar;
        d0[0] = a0.x; d0[AROW] = a0.y; d0[2 * AROW] = a0.z; d0[3 * AROW] = a0.w;
        if (hasB) {
            float4 b0 = *(const float4*)gb;
            float* d1 = Bs + bq * 4 * BROW + br;
            d1[0] = b0.x; d1[BROW] = b0.y; d1[2 * BROW] = b0.z; d1[3 * BROW] = b0.w;
        }
    }
    __syncthreads();

#pragma unroll 1
    for (int g = 0; g < NKT; g++) {
        const int buf = g & 1;
        float4 na, nb;
        const bool more = (g + 1) < NKT;
        if (more) {
            const size_t ko = (size_t)(g + 1) * BK;
            na = *(const float4*)(ga + ko);
            if (hasB) nb = *(const float4*)(gb + ko);
        }

        const float* ap = As + buf * ABUF + ty * 8;
        const float* bp = Bs + buf * BBUF + tx * 8;
#pragma unroll
        for (int k = 0; k < BK; k++) {
            ulonglong2 aA = *(const ulonglong2*)(ap + k * AROW);
            ulonglong2 aB = *(const ulonglong2*)(ap + k * AROW + 4);
            float4 b0 = *(const float4*)(bp + k * BROW);
            float4 b1 = *(const float4*)(bp + k * BROW + 4);
            const unsigned long long apk[4] = {aA.x, aA.y, aB.x, aB.y};
            const unsigned long long bd[8] = {
                dup2(b0.x), dup2(b0.y), dup2(b0.z), dup2(b0.w),
                dup2(b1.x), dup2(b1.y), dup2(b1.z), dup2(b1.w)};
#pragma unroll
            for (int i = 0; i < 4; i++)
#pragma unroll
                for (int j = 0; j < 8; j++)
                    ffma2(acc[i][j], apk[i], bd[j]);
        }

        // k=2048 boundary: stash first-half chains, restart accumulators
        if (g == HALF_TILES - 1) {
            unsigned long long* sp = spill + tid * 32;
#pragma unroll
            for (int i = 0; i < 4; i++)
#pragma unroll
                for (int j = 0; j < 8; j++) {
                    sp[i * 8 + j] = acc[i][j];
                    acc[i][j] = 0ull;
                }
        }

        __syncthreads();
        if (more) {
            const int nbuf = buf ^ 1;
            float* d0 = As + nbuf * ABUF + aq * 4 * AROW + ar;
            d0[0] = na.x; d0[AROW] = na.y; d0[2 * AROW] = na.z; d0[3 * AROW] = na.w;
            if (hasB) {
                float* d1 = Bs + nbuf * BBUF + bq * 4 * BROW + br;
                d1[0] = nb.x; d1[BROW] = nb.y; d1[2 * BROW] = nb.z; d1[3 * BROW] = nb.w;
            }
        }
        __syncthreads();
    }

    // epilogue: S = t0 + t1 (per-lane), +bias, exact fmod
    const int col = n0 + tx * 8;
    const float4 bb0 = *(const float4*)(bias + col);
    const float4 bb1 = *(const float4*)(bias + col + 4);
    const float bc[8] = {bb0.x, bb0.y, bb0.z, bb0.w, bb1.x, bb1.y, bb1.z, bb1.w};
    const unsigned long long* sp = spill + tid * 32;

#pragma unroll
    for (int i = 0; i < 4; i++) {
        unsigned long long S[8];
#pragma unroll
        for (int j = 0; j < 8; j++) S[j] = addf32x2(sp[i * 8 + j], acc[i][j]);

        const int rlo = m0 + ty * 8 + i * 2;
        float4 v0, v1, u0, u1;
        v0.x = fmod2f(__uint_as_float((unsigned)S[0]) + bc[0]);
        v0.y = fmod2f(__uint_as_float((unsigned)S[1]) + bc[1]);
        v0.z = fmod2f(__uint_as_float((unsigned)S[2]) + bc[2]);
        v0.w = fmod2f(__uint_as_float((unsigned)S[3]) + bc[3]);
        v1.x = fmod2f(__uint_as_float((unsigned)S[4]) + bc[4]);
        v1.y = fmod2f(__uint_as_float((unsigned)S[5]) + bc[5]);
        v1.z = fmod2f(__uint_as_float((unsigned)S[6]) + bc[6]);
        v1.w = fmod2f(__uint_as_float((unsigned)S[7]) + bc[7]);
        u0.x = fmod2f(__uint_as_float((unsigned)(S[0] >> 32)) + bc[0]);
        u0.y = fmod2f(__uint_as_float((unsigned)(S[1] >> 32)) + bc[1]);
        u0.z = fmod2f(__uint_as_float((unsigned)(S[2] >> 32)) + bc[2]);
        u0.w = fmod2f(__uint_as_float((unsigned)(S[3] >> 32)) + bc[3]);
        u1.x = fmod2f(__uint_as_float((unsigned)(S[4] >> 32)) + bc[4]);
        u1.y = fmod2f(__uint_as_float((unsigned)(S[5] >> 32)) + bc[5]);
        u1.z = fmod2f(__uint_as_float((unsigned)(S[6] >> 32)) + bc[6]);
        u1.w = fmod2f(__uint_as_float((unsigned)(S[7] >> 32)) + bc[7]);
        *(float4*)(out + (size_t)rlo * NDIM + col) = v0;
        *(float4*)(out + (size_t)rlo * NDIM + col + 4) = v1;
        *(float4*)(out + (size_t)(rlo + 1) * NDIM + col) = u0;
        *(float4*)(out + (size_t)(rlo + 1) * NDIM + col + 4) = u1;
    }
}

extern "C" void kernel_launch(void* const* d_in, const int* in_sizes, int n_in,
                              void* d_out, int out_size) {
    const float* x = (const float*)d_in[0];
    const float* w = (const float*)d_in[1];
    const float* bias = (const float*)d_in[2];
    float* out = (float*)d_out;
    (void)in_sizes; (void)n_in; (void)out_size;

    static int attr_set = 0;
    if (!attr_set) {
        cudaFuncSetAttribute(k_sgemm_fmod,
                             cudaFuncAttributeMaxDynamicSharedMemorySize, SMEM_BYTES);
        attr_set = 1;
    }
    dim3 grid(NDIM / BN, MDIM / BM);   // (32, 32)
    k_sgemm_fmod<<<grid, 512, SMEM_BYTES>>>(x, w, bias, out);
}

// round 17
// speedup vs baseline: 1.1090x; 1.1090x over previous
#include <cuda_runtime.h>
#include <cstdint>

// Problem dims
#define MDIM 8192
#define NDIM 4096
#define KDIM 4096

// Tiling: CTA 256x64, 256 threads, thread tile 16x4 (8 m-pairs x 4 n), 2 CTAs/SM
#define BM 256
#define BN 64
#define BK 8
#define NKT (KDIM / BK)        // 512
#define HALF_TILES 256         // k=2048 boundary

#define AROW 264               // 256 + 8 pad floats
#define BROW 68                // 64 + 4 pad floats
#define ABUF (BK * AROW)       // 2112 floats
#define BBUF (BK * BROW)       // 544 floats
#define BS_OFFF (2 * ABUF)
#define SPILL_OFF ((2 * ABUF + 2 * BBUF) * 4)        // 21248 bytes
#define SMEM_BYTES (SPILL_OFF + 256 * 32 * 8)        // 86784 (x2 CTAs = 173KB)

// Reference chain (bitwise-locked): per output two ascending FMA chains over
// k-halves of 2048 (each from 0), merged with one add, +bias, truncated fmod.
// f32x2 lanes carry two DIFFERENT outputs (adjacent m rows).

__device__ __forceinline__ float fmod2f(float v) {
    return fmaf(-2.0f, truncf(v * 0.5f), v);
}
__device__ __forceinline__ void ffma2(unsigned long long& d,
                                      unsigned long long a,
                                      unsigned long long b) {
    asm("fma.rn.f32x2 %0, %1, %2, %0;" : "+l"(d) : "l"(a), "l"(b));
}
__device__ __forceinline__ unsigned long long addf32x2(unsigned long long a,
                                                       unsigned long long b) {
    unsigned long long d;
    asm("add.rn.f32x2 %0, %1, %2;" : "=l"(d) : "l"(a), "l"(b));
    return d;
}
__device__ __forceinline__ unsigned long long dup2(float b) {
    unsigned long long d;
    asm("mov.b64 %0, {%1, %1};" : "=l"(d) : "f"(b));
    return d;
}

__global__ void __launch_bounds__(256, 2)
k_sgemm_fmod(const float* __restrict__ X, const float* __restrict__ W,
             const float* __restrict__ bias, float* __restrict__ out) {
    extern __shared__ char smem[];
    float* As = (float*)smem;                      // [2][8][264]
    float* Bs = As + BS_OFFF;                      // [2][8][68]
    unsigned long long* spill =
        (unsigned long long*)(smem + SPILL_OFF);   // [256][32]

    const int tid = threadIdx.x;
    const int tx = tid & 15;          // n: 16 thr x 4 cols
    const int ty = tid >> 4;          // m: 16 thr x 16 rows
    const int m0 = blockIdx.y * BM;
    const int n0 = blockIdx.x * BN;

    // loaders: A = 512 float4 chunks (2/thread); B = 128 chunks (tid<128)
    const int ar = tid >> 1, aq = tid & 1;             // chunk tid -> row ar
    const float* ga0 = X + (size_t)(m0 + ar) * KDIM + aq * 4;
    const float* ga1 = X + (size_t)(m0 + ar + 128) * KDIM + aq * 4;
    const bool hasB = tid < 128;
    const int br = tid >> 1, bq = tid & 1;
    const float* gb = W + (size_t)(n0 + (hasB ? br : 0)) * KDIM + bq * 4;

    unsigned long long acc[8][4];   // 8 m-pairs x 4 n
#pragma unroll
    for (int i = 0; i < 8; i++)
#pragma unroll
        for (int j = 0; j < 4; j++) acc[i][j] = 0ull;

    // prologue: tile 0 -> buf 0
    {
        float4 a0 = *(const float4*)ga0;
        float4 a1 = *(const float4*)ga1;
        float* d0 = As + aq * 4 * AROW + ar;
        float* d1 = As + aq * 4 * AROW + ar + 128;
        d0[0] = a0.x; d0[AROW] = a0.y; d0[2 * AROW] = a0.z; d0[3 * AROW] = a0.w;
        d1[0] = a1.x; d1[AROW] = a1.y; d1[2 * AROW] = a1.z; d1[3 * AROW] = a1.w;
        if (hasB) {
            float4 b0 = *(const float4*)gb;
            float* d2 = Bs + bq * 4 * BROW + br;
            d2[0] = b0.x; d2[BROW] = b0.y; d2[2 * BROW] = b0.z; d2[3 * BROW] = b0.w;
        }
    }
    __syncthreads();

#pragma unroll 1
    for (int g = 0; g < NKT; g++) {
        const int buf = g & 1;
        float4 na0, na1, nb;
        const bool more = (g + 1) < NKT;
        if (more) {
            const size_t ko = (size_t)(g + 1) * BK;
            na0 = *(const float4*)(ga0 + ko);
            na1 = *(const float4*)(ga1 + ko);
            if (hasB) nb = *(const float4*)(gb + ko);
        }

        const float* ap = As + buf * ABUF + ty * 16;
        const float* bp = Bs + buf * BBUF + tx * 4;
#pragma unroll
        for (int k = 0; k < BK; k++) {
            ulonglong2 aA = *(const ulonglong2*)(ap + k * AROW);
            ulonglong2 aB = *(const ulonglong2*)(ap + k * AROW + 4);
            ulonglong2 aC = *(const ulonglong2*)(ap + k * AROW + 8);
            ulonglong2 aD = *(const ulonglong2*)(ap + k * AROW + 12);
            float4 b0 = *(const float4*)(bp + k * BROW);
            const unsigned long long apk[8] = {aA.x, aA.y, aB.x, aB.y,
                                               aC.x, aC.y, aD.x, aD.y};
            const unsigned long long bd[4] = {dup2(b0.x), dup2(b0.y),
                                              dup2(b0.z), dup2(b0.w)};
#pragma unroll
            for (int i = 0; i < 8; i++)
#pragma unroll
                for (int j = 0; j < 4; j++)
                    ffma2(acc[i][j], apk[i], bd[j]);
        }

        // k=2048 boundary: stash first-half chains, restart accumulators
        if (g == HALF_TILES - 1) {
            unsigned long long* sp = spill + tid * 32;
#pragma unroll
            for (int i = 0; i < 8; i++)
#pragma unroll
                for (int j = 0; j < 4; j++) {
                    sp[i * 4 + j] = acc[i][j];
                    acc[i][j] = 0ull;
                }
        }

        __syncthreads();
        if (more) {
            const int nbuf = buf ^ 1;
            float* d0 = As + nbuf * ABUF + aq * 4 * AROW + ar;
            float* d1 = As + nbuf * ABUF + aq * 4 * AROW + ar + 128;
            d0[0] = na0.x; d0[AROW] = na0.y; d0[2 * AROW] = na0.z; d0[3 * AROW] = na0.w;
            d1[0] = na1.x; d1[AROW] = na1.y; d1[2 * AROW] = na1.z; d1[3 * AROW] = na1.w;
            if (hasB) {
                float* d2 = Bs + nbuf * BBUF + bq * 4 * BROW + br;
                d2[0] = nb.x; d2[BROW] = nb.y; d2[2 * BROW] = nb.z; d2[3 * BROW] = nb.w;
            }
        }
        __syncthreads();
    }

    // epilogue: S = t0 + t1 (per-lane), +bias, exact fmod
    const int col = n0 + tx * 4;
    const float4 bb = *(const float4*)(bias + col);
    const float bc[4] = {bb.x, bb.y, bb.z, bb.w};
    const unsigned long long* sp = spill + tid * 32;

#pragma unroll
    for (int i = 0; i < 8; i++) {
        unsigned long long S[4];
#pragma unroll
        for (int j = 0; j < 4; j++) S[j] = addf32x2(sp[i * 4 + j], acc[i][j]);

        const int rlo = m0 + ty * 16 + i * 2;
        float4 v, u;
        v.x = fmod2f(__uint_as_float((unsigned)S[0]) + bc[0]);
        v.y = fmod2f(__uint_as_float((unsigned)S[1]) + bc[1]);
        v.z = fmod2f(__uint_as_float((unsigned)S[2]) + bc[2]);
        v.w = fmod2f(__uint_as_float((unsigned)S[3]) + bc[3]);
        u.x = fmod2f(__uint_as_float((unsigned)(S[0] >> 32)) + bc[0]);
        u.y = fmod2f(__uint_as_float((unsigned)(S[1] >> 32)) + bc[1]);
        u.z = fmod2f(__uint_as_float((unsigned)(S[2] >> 32)) + bc[2]);
        u.w = fmod2f(__uint_as_float((unsigned)(S[3] >> 32)) + bc[3]);
        *(float4*)(out + (size_t)rlo * NDIM + col) = v;
        *(float4*)(out + (size_t)(rlo + 1) * NDIM + col) = u;
    }
}

extern "C" void kernel_launch(void* const* d_in, const int* in_sizes, int n_in,
                              void* d_out, int out_size) {
    const float* x = (const float*)d_in[0];
    const float* w = (const float*)d_in[1];
    const float* bias = (const float*)d_in[2];
    float* out = (float*)d_out;
    (void)in_sizes; (void)n_in; (void)out_size;

    static int attr_set = 0;
    if (!attr_set) {
        cudaFuncSetAttribute(k_sgemm_fmod,
                             cudaFuncAttributeMaxDynamicSharedMemorySize, SMEM_BYTES);
        attr_set = 1;
    }
    dim3 grid(NDIM / BN, MDIM / BM);   // (64, 32)
    k_sgemm_fmod<<<grid, 256, SMEM_BYTES>>>(x, w, bias, out);
}